// round 14
// baseline (speedup 1.0000x reference)
#include <cuda_runtime.h>
#include <math.h>

#define Bsz 512
#define Tsz 512
#define Dsz 256
#define NC  4           // T-chunks per batch row
#define CROWS (Tsz/NC)  // 128 rows per chunk
#define BB  4           // batch rows per k4 CTA

// out = [p (512) | T_event (512x513) | L_t (512x256) | M_t (512)]
#define OFF_TE 512
#define OFF_L  (512 + 512*513)
#define OFF_M  (OFF_L + 512*256)

__device__ __align__(16) float g_qpart[Bsz*NC*Dsz];
__device__ float g_cnt4[Bsz*NC];
__device__ float g_max4[Bsz*NC];
__device__ float g_tmax[Bsz];
__device__ __align__(16) float g_u[Bsz*Dsz];
__device__ __align__(16) float g_ypart[Bsz*NC*Dsz];
__device__ float g_m4[Bsz*NC], g_Z4[Bsz*NC], g_S4[Bsz*NC];
__device__ __align__(16) float g_WVt[Dsz*Dsz];   // WVt[d][e] = WV[e][d]

// ---------------- K1: pass A partials (grid: NC x Bsz) — champion code ----------------
__global__ void __launch_bounds__(256)
k1a(const float* __restrict__ wf, const float* __restrict__ ts,
    const unsigned char* __restrict__ pad) {
    int c = blockIdx.x, b = blockIdx.y;
    int tid = threadIdx.x;
    int warp = tid >> 5, lane = tid & 31;
    int t0 = c * CROWS;

    __shared__ float s_valid[CROWS];
    __shared__ float s_rm[CROWS], s_rc[CROWS];
    __shared__ __align__(16) float s_acc[8*Dsz];

    if (tid < CROWS) {
        float v = pad[b*Tsz + t0 + tid] ? 0.f : 1.f;
        s_valid[tid] = v;
        float tv = ts[b*Tsz + t0 + tid];
        s_rm[tid] = (v > 0.f) ? tv : -3.0e38f;
        s_rc[tid] = v;
    }
    __syncthreads();
    for (int s = CROWS/2; s > 0; s >>= 1) {
        if (tid < s) {
            s_rm[tid] = fmaxf(s_rm[tid], s_rm[tid+s]);
            s_rc[tid] += s_rc[tid+s];
        }
        __syncthreads();
    }

    const float4* wf4 = (const float4*)(wf + (size_t)b*Tsz*Dsz + (size_t)t0*Dsz);
    {
        float4 A = make_float4(0.f,0.f,0.f,0.f);
        float4 B = make_float4(0.f,0.f,0.f,0.f);
        #pragma unroll 4
        for (int t = warp*2; t < CROWS; t += 16) {
            float4 wa0 = wf4[t*64 + lane];
            float4 wb0 = wf4[t*64 + 32 + lane];
            float4 wa1 = wf4[(t+1)*64 + lane];
            float4 wb1 = wf4[(t+1)*64 + 32 + lane];
            float v0 = s_valid[t], v1 = s_valid[t+1];
            A.x = fmaf(wa0.x, v0, fmaf(wa1.x, v1, A.x));
            A.y = fmaf(wa0.y, v0, fmaf(wa1.y, v1, A.y));
            A.z = fmaf(wa0.z, v0, fmaf(wa1.z, v1, A.z));
            A.w = fmaf(wa0.w, v0, fmaf(wa1.w, v1, A.w));
            B.x = fmaf(wb0.x, v0, fmaf(wb1.x, v1, B.x));
            B.y = fmaf(wb0.y, v0, fmaf(wb1.y, v1, B.y));
            B.z = fmaf(wb0.z, v0, fmaf(wb1.z, v1, B.z));
            B.w = fmaf(wb0.w, v0, fmaf(wb1.w, v1, B.w));
        }
        float4* sa4 = (float4*)s_acc;
        sa4[warp*64 + lane]      = A;
        sa4[warp*64 + 32 + lane] = B;
    }
    __syncthreads();

    int bc = b*NC + c;
    {
        float q = 0.f;
        #pragma unroll
        for (int w = 0; w < 8; w++) q += s_acc[w*Dsz + tid];
        g_qpart[(size_t)bc*Dsz + tid] = q;
    }
    if (tid == 0) { g_max4[bc] = s_rm[0]; g_cnt4[bc] = s_rc[0]; }
}

// ---- K2: reduce q/tmax; Q=q@WQ^T; u=Q@WK (4 b/CTA, grid 128) + WVt transpose tail ----
__global__ void __launch_bounds__(256)
k_qu(const float* __restrict__ WQ, const float* __restrict__ WK,
     const float* __restrict__ WV) {
    int b0 = blockIdx.x * 4, tid = threadIdx.x;
    int warp = tid >> 5, lane = tid & 31;
    __shared__ __align__(16) float s_q[4][Dsz];
    __shared__ __align__(16) float s_Q[4][Dsz];

    #pragma unroll
    for (int g = 0; g < 4; g++) {
        int b = b0 + g;
        float q = 0.f, cnt = 0.f, mx = -3.0e38f;
        #pragma unroll
        for (int c = 0; c < NC; c++) {
            q   += g_qpart[(size_t)(b*NC + c)*Dsz + tid];
            cnt += g_cnt4[b*NC + c];
            mx   = fmaxf(mx, g_max4[b*NC + c]);
        }
        s_q[g][tid] = q / fmaxf(cnt, 1.f);
        if (tid == 0) g_tmax[b] = mx;
    }
    // WVt transpose tail: CTA i transposes rows d = 2i, 2i+1 of WVt
    // (strided reads of WV column d, coalesced writes) — independent of s_q work.
    {
        int d0 = blockIdx.x * 2;
        g_WVt[(size_t)d0*Dsz + tid]     = WV[(size_t)tid*Dsz + d0];
        g_WVt[(size_t)(d0+1)*Dsz + tid] = WV[(size_t)tid*Dsz + d0 + 1];
    }
    __syncthreads();

    // Stage 1: Q[g][e] = sum_d q[g][d]*WQ[e,d] — warp per row e, 2 rows in flight
    {
        float4 qA[4], qB[4];
        #pragma unroll
        for (int g = 0; g < 4; g++) {
            const float4* q4 = (const float4*)s_q[g];
            qA[g] = q4[lane*2]; qB[g] = q4[lane*2 + 1];
        }
        #pragma unroll 2
        for (int i = 0; i < 32; i += 2) {
            int e0 = warp*32 + i, e1 = e0 + 1;
            const float4* wr0 = (const float4*)(WQ + (size_t)e0*Dsz);
            const float4* wr1 = (const float4*)(WQ + (size_t)e1*Dsz);
            float4 w0A = wr0[lane*2], w0B = wr0[lane*2 + 1];
            float4 w1A = wr1[lane*2], w1B = wr1[lane*2 + 1];
            float d[8];
            #pragma unroll
            for (int g = 0; g < 4; g++) {
                d[g]   = w0A.x*qA[g].x + w0A.y*qA[g].y + w0A.z*qA[g].z + w0A.w*qA[g].w
                       + w0B.x*qB[g].x + w0B.y*qB[g].y + w0B.z*qB[g].z + w0B.w*qB[g].w;
                d[4+g] = w1A.x*qA[g].x + w1A.y*qA[g].y + w1A.z*qA[g].z + w1A.w*qA[g].w
                       + w1B.x*qB[g].x + w1B.y*qB[g].y + w1B.z*qB[g].z + w1B.w*qB[g].w;
            }
            #pragma unroll
            for (int o = 16; o > 0; o >>= 1) {
                #pragma unroll
                for (int k = 0; k < 8; k++) d[k] += __shfl_xor_sync(0xffffffffu, d[k], o);
            }
            if (lane == 0) {
                #pragma unroll
                for (int g = 0; g < 4; g++) { s_Q[g][e0] = d[g]; s_Q[g][e1] = d[4+g]; }
            }
        }
    }
    __syncthreads();

    // Stage 2: u[g][d2] = sum_e Q[g][e]*WK[e,d2] — threads over d2 (coalesced)
    {
        float a[4] = {0.f, 0.f, 0.f, 0.f};
        const float* Wp = WK + tid;
        #pragma unroll 8
        for (int e = 0; e < Dsz; e++) {
            float w = __ldg(Wp + (size_t)e*Dsz);
            #pragma unroll
            for (int g = 0; g < 4; g++) a[g] = fmaf(s_Q[g][e], w, a[g]);
        }
        #pragma unroll
        for (int g = 0; g < 4; g++) g_u[(size_t)(b0+g)*Dsz + tid] = a[g];
    }
}

// ---------------- K3: pass B partials (grid: NC x Bsz) — joint two-row rescale (champion) ----------------
__global__ void __launch_bounds__(256)
k3a(const float* __restrict__ wf, const float* __restrict__ ts,
    const unsigned char* __restrict__ pad) {
    int c = blockIdx.x, b = blockIdx.y;
    int tid = threadIdx.x;
    int warp = tid >> 5, lane = tid & 31;
    int t0 = c * CROWS;

    __shared__ float s_lam[CROWS];
    __shared__ float s_valid[CROWS];
    __shared__ float s_m[8], s_Z[8], s_S[8];
    __shared__ __align__(16) float s_yp[8*Dsz];

    float tmaxv = g_tmax[b];
    if (tid < CROWS) {
        float v = pad[b*Tsz + t0 + tid] ? 0.f : 1.f;
        float dt = fmaxf(tmaxv - ts[b*Tsz + t0 + tid], 0.f) * (1.f/86400.f);
        s_lam[tid] = __expf(-0.5f*dt) * v;
        s_valid[tid] = v;
    }
    __syncthreads();

    const float4* u4 = (const float4*)(g_u + (size_t)b*Dsz);
    float4 ua = u4[lane], ub = u4[lane + 32];
    const float4* wf4 = (const float4*)(wf + (size_t)b*Tsz*Dsz + (size_t)t0*Dsz);

    float m = -3.0e38f, Z = 0.f, S = 0.f;
    float4 ya = make_float4(0.f,0.f,0.f,0.f);
    float4 yb = make_float4(0.f,0.f,0.f,0.f);

    #pragma unroll 2
    for (int t = warp*2; t < CROWS; t += 16) {
        float4 wa0 = wf4[t*64 + lane];
        float4 wb0 = wf4[t*64 + 32 + lane];
        float4 wa1 = wf4[(t+1)*64 + lane];
        float4 wb1 = wf4[(t+1)*64 + 32 + lane];
        float d0 = wa0.x*ua.x + wa0.y*ua.y + wa0.z*ua.z + wa0.w*ua.w
                 + wb0.x*ub.x + wb0.y*ub.y + wb0.z*ub.z + wb0.w*ub.w;
        float d1 = wa1.x*ua.x + wa1.y*ua.y + wa1.z*ua.z + wa1.w*ua.w
                 + wb1.x*ub.x + wb1.y*ub.y + wb1.z*ub.z + wb1.w*ub.w;
        #pragma unroll
        for (int o = 16; o > 0; o >>= 1) {
            d0 += __shfl_xor_sync(0xffffffffu, d0, o);
            d1 += __shfl_xor_sync(0xffffffffu, d1, o);
        }
        float s0 = d0 * 0.0625f;
        float s1 = d1 * 0.0625f;
        float nm = fmaxf(m, fmaxf(s0, s1));
        float sc = __expf(m - nm);
        float e0 = __expf(s0 - nm);
        float e1 = __expf(s1 - nm);
        float v0 = s_valid[t], v1 = s_valid[t+1];
        float g0 = s_lam[t]   * e0;
        float g1 = s_lam[t+1] * e1;
        Z = fmaf(Z, sc, fmaf(v0, e0, v1*e1));
        S = fmaf(S, sc, g0 + g1);
        ya.x = fmaf(ya.x, sc, fmaf(g0, wa0.x, g1*wa1.x));
        ya.y = fmaf(ya.y, sc, fmaf(g0, wa0.y, g1*wa1.y));
        ya.z = fmaf(ya.z, sc, fmaf(g0, wa0.z, g1*wa1.z));
        ya.w = fmaf(ya.w, sc, fmaf(g0, wa0.w, g1*wa1.w));
        yb.x = fmaf(yb.x, sc, fmaf(g0, wb0.x, g1*wb1.x));
        yb.y = fmaf(yb.y, sc, fmaf(g0, wb0.y, g1*wb1.y));
        yb.z = fmaf(yb.z, sc, fmaf(g0, wb0.z, g1*wb1.z));
        yb.w = fmaf(yb.w, sc, fmaf(g0, wb0.w, g1*wb1.w));
        m = nm;
    }

    if (lane == 0) s_m[warp] = m;
    __syncthreads();
    float M = s_m[0];
    #pragma unroll
    for (int w = 1; w < 8; w++) M = fmaxf(M, s_m[w]);
    float scw = __expf(m - M);
    if (lane == 0) { s_Z[warp] = Z*scw; s_S[warp] = S*scw; }
    {
        float4* syp4 = (float4*)s_yp;
        syp4[warp*64 + lane]      = make_float4(ya.x*scw, ya.y*scw, ya.z*scw, ya.w*scw);
        syp4[warp*64 + 32 + lane] = make_float4(yb.x*scw, yb.y*scw, yb.z*scw, yb.w*scw);
    }
    __syncthreads();

    int bc = b*NC + c;
    {
        float yv = 0.f;
        #pragma unroll
        for (int w = 0; w < 8; w++) yv += s_yp[w*Dsz + tid];
        g_ypart[(size_t)bc*Dsz + tid] = yv;
    }
    if (tid == 0) {
        float Zt = 0.f, St = 0.f;
        #pragma unroll
        for (int w = 0; w < 8; w++) { Zt += s_Z[w]; St += s_S[w]; }
        g_m4[bc] = M; g_Z4[bc] = Zt; g_S4[bc] = St;
    }
}

// ------- K4: combine + L = y@WVt (thread-per-e, no shfl) + register-local epilogue (BB=4, grid 128) -------
__global__ void __launch_bounds__(256)
k4(const float* __restrict__ prevL, const float* __restrict__ prevM,
   const float* __restrict__ clsw, const float* __restrict__ clsb,
   float* __restrict__ out) {
    int b0 = blockIdx.x * BB, tid = threadIdx.x;
    int warp = tid >> 5, lane = tid & 31;
    __shared__ __align__(16) float s_y[BB][Dsz];
    __shared__ float s_w1[BB][8], s_w2[BB][8];

    #pragma unroll
    for (int g = 0; g < BB; g++) {
        int b = b0 + g;
        float m0 = g_m4[b*NC+0], m1 = g_m4[b*NC+1], m2 = g_m4[b*NC+2], m3 = g_m4[b*NC+3];
        float M = fmaxf(fmaxf(m0, m1), fmaxf(m2, m3));
        float c0 = __expf(m0 - M), c1 = __expf(m1 - M), c2 = __expf(m2 - M), c3 = __expf(m3 - M);
        float Zt = g_Z4[b*NC+0]*c0 + g_Z4[b*NC+1]*c1 + g_Z4[b*NC+2]*c2 + g_Z4[b*NC+3]*c3;
        float St = g_S4[b*NC+0]*c0 + g_S4[b*NC+1]*c1 + g_S4[b*NC+2]*c2 + g_S4[b*NC+3]*c3;
        float yv = g_ypart[(size_t)(b*NC+0)*Dsz+tid]*c0 + g_ypart[(size_t)(b*NC+1)*Dsz+tid]*c1
                 + g_ypart[(size_t)(b*NC+2)*Dsz+tid]*c2 + g_ypart[(size_t)(b*NC+3)*Dsz+tid]*c3;
        float denom = St + 1e-8f*Zt;
        float inv = denom > 0.f ? 1.f/denom : 0.f;
        s_y[g][tid] = yv * inv;
    }
    __syncthreads();

    // L[g][e=tid] = sum_d y[g][d] * WVt[d][e] — coalesced LDG over e, LDS.128 broadcasts
    float a[BB] = {0.f, 0.f, 0.f, 0.f};
    {
        const float* Wp = g_WVt + tid;
        #pragma unroll 4
        for (int i = 0; i < Dsz; i += 4) {
            float w0 = Wp[(size_t)(i+0)*Dsz];
            float w1 = Wp[(size_t)(i+1)*Dsz];
            float w2 = Wp[(size_t)(i+2)*Dsz];
            float w3 = Wp[(size_t)(i+3)*Dsz];
            #pragma unroll
            for (int g = 0; g < BB; g++) {
                float4 yv = *(const float4*)&s_y[g][i];
                a[g] = fmaf(yv.x, w0, fmaf(yv.y, w1, fmaf(yv.z, w2, fmaf(yv.w, w3, a[g]))));
            }
        }
    }

    // epilogue (L value lives in a[g] at e=tid — no smem roundtrip)
    float cw1 = clsw[tid], cw2 = clsw[Dsz + tid];
    float dlg[BB];
    #pragma unroll
    for (int g = 0; g < BB; g++) {
        int b = b0 + g;
        float dl = a[g] - prevL[(size_t)b*Dsz + tid];
        dlg[g] = dl;
        float r1 = dl*dl;
        float r2 = fmaf(a[g], cw1, dl*cw2);
        #pragma unroll
        for (int o = 16; o > 0; o >>= 1) {
            r1 += __shfl_xor_sync(0xffffffffu, r1, o);
            r2 += __shfl_xor_sync(0xffffffffu, r2, o);
        }
        if (lane == 0) { s_w1[g][warp] = r1; s_w2[g][warp] = r2; }
    }
    __syncthreads();
    #pragma unroll
    for (int g = 0; g < BB; g++) {
        int b = b0 + g;
        size_t te = (size_t)OFF_TE + (size_t)b*513;
        out[te + tid]       = a[g];
        out[te + 256 + tid] = dlg[g];
        out[OFF_L + (size_t)b*Dsz + tid] = a[g];
        if (tid == 0) {
            float R1 = 0.f, R2 = 0.f;
            #pragma unroll
            for (int w = 0; w < 8; w++) { R1 += s_w1[g][w]; R2 += s_w2[g][w]; }
            float Mt = 0.9f*prevM[b] + 0.1f*sqrtf(R1);
            out[OFF_M + b] = Mt;
            out[te + 512]  = Mt;
            out[b] = R2 + Mt*clsw[2*Dsz] + clsb[0];
        }
    }
}

extern "C" void kernel_launch(void* const* d_in, const int* in_sizes, int n_in,
                              void* d_out, int out_size) {
    const float*         wf    = (const float*)d_in[0];
    const float*         ts    = (const float*)d_in[1];
    const float*         prevL = (const float*)d_in[2];
    const float*         prevM = (const float*)d_in[3];
    const unsigned char* pad   = (const unsigned char*)d_in[4];
    const float*         WQ    = (const float*)d_in[5];
    const float*         WK    = (const float*)d_in[6];
    const float*         WV    = (const float*)d_in[7];
    const float*         clsw  = (const float*)d_in[8];
    const float*         clsb  = (const float*)d_in[9];
    float* out = (float*)d_out;

    k1a <<<dim3(NC, Bsz), 256>>>(wf, ts, pad);
    k_qu<<<Bsz/4, 256>>>(WQ, WK, WV);
    k3a <<<dim3(NC, Bsz), 256>>>(wf, ts, pad);
    k4  <<<Bsz/BB, 256>>>(prevL, prevM, clsw, clsb, out);
}

// round 15
// speedup vs baseline: 1.0880x; 1.0880x over previous
#include <cuda_runtime.h>
#include <math.h>

#define Bsz 512
#define Tsz 512
#define Dsz 256
#define NC  4           // T-chunks per batch row
#define CROWS (Tsz/NC)  // 128 rows per chunk
#define BB  4           // batch rows per small-kernel CTA

// out = [p (512) | T_event (512x513) | L_t (512x256) | M_t (512)]
#define OFF_TE 512
#define OFF_L  (512 + 512*513)
#define OFF_M  (OFF_L + 512*256)

__device__ __align__(16) float g_qpart[Bsz*NC*Dsz];
__device__ float g_cnt4[Bsz*NC];
__device__ float g_max4[Bsz*NC];
__device__ float g_tmax[Bsz];
__device__ __align__(16) float g_u[Bsz*Dsz];
__device__ __align__(16) float g_ypart[Bsz*NC*Dsz];
__device__ float g_m4[Bsz*NC], g_Z4[Bsz*NC], g_S4[Bsz*NC];
__device__ __align__(16) float g_G[Dsz*Dsz];     // G = WQ^T @ WK
__device__ __align__(16) float g_WVt[Dsz*Dsz];   // WVt[d][e] = WV[e][d]

// ---- K1: pass A partials (grid: (NC+1) x Bsz); c==NC blocks do prep (G, WVt) overlapped ----
__global__ void __launch_bounds__(256)
k1a(const float* __restrict__ wf, const float* __restrict__ ts,
    const unsigned char* __restrict__ pad,
    const float* __restrict__ WQ, const float* __restrict__ WK,
    const float* __restrict__ WV) {
    int c = blockIdx.x, b = blockIdx.y;
    int tid = threadIdx.x;

    if (c == NC) {
        if (b < 64) {
            // G rows d1 = b*4 .. b*4+3 : G[d1][d2] = sum_e WQ[e][d1]*WK[e][d2]
            int d1b = b * 4;
            float a0 = 0.f, a1 = 0.f, a2 = 0.f, a3 = 0.f;
            #pragma unroll 4
            for (int e = 0; e < Dsz; e++) {
                float wk = __ldg(WK + (size_t)e*Dsz + tid);
                a0 = fmaf(__ldg(WQ + (size_t)e*Dsz + d1b + 0), wk, a0);
                a1 = fmaf(__ldg(WQ + (size_t)e*Dsz + d1b + 1), wk, a1);
                a2 = fmaf(__ldg(WQ + (size_t)e*Dsz + d1b + 2), wk, a2);
                a3 = fmaf(__ldg(WQ + (size_t)e*Dsz + d1b + 3), wk, a3);
            }
            g_G[(size_t)(d1b+0)*Dsz + tid] = a0;
            g_G[(size_t)(d1b+1)*Dsz + tid] = a1;
            g_G[(size_t)(d1b+2)*Dsz + tid] = a2;
            g_G[(size_t)(d1b+3)*Dsz + tid] = a3;
        } else if (b < 192) {
            // WVt rows d = (b-64)*2, +1  (strided reads, coalesced writes)
            int d0 = (b - 64) * 2;
            g_WVt[(size_t)d0*Dsz + tid]     = __ldg(WV + (size_t)tid*Dsz + d0);
            g_WVt[(size_t)(d0+1)*Dsz + tid] = __ldg(WV + (size_t)tid*Dsz + d0 + 1);
        }
        return;
    }

    int warp = tid >> 5, lane = tid & 31;
    int t0 = c * CROWS;

    __shared__ float s_valid[CROWS];
    __shared__ float s_rm[CROWS], s_rc[CROWS];
    __shared__ __align__(16) float s_acc[8*Dsz];

    if (tid < CROWS) {
        float v = pad[b*Tsz + t0 + tid] ? 0.f : 1.f;
        s_valid[tid] = v;
        float tv = ts[b*Tsz + t0 + tid];
        s_rm[tid] = (v > 0.f) ? tv : -3.0e38f;
        s_rc[tid] = v;
    }
    __syncthreads();
    for (int s = CROWS/2; s > 0; s >>= 1) {
        if (tid < s) {
            s_rm[tid] = fmaxf(s_rm[tid], s_rm[tid+s]);
            s_rc[tid] += s_rc[tid+s];
        }
        __syncthreads();
    }

    const float4* wf4 = (const float4*)(wf + (size_t)b*Tsz*Dsz + (size_t)t0*Dsz);
    {
        float4 A = make_float4(0.f,0.f,0.f,0.f);
        float4 B = make_float4(0.f,0.f,0.f,0.f);
        #pragma unroll 4
        for (int t = warp*2; t < CROWS; t += 16) {
            float4 wa0 = wf4[t*64 + lane];
            float4 wb0 = wf4[t*64 + 32 + lane];
            float4 wa1 = wf4[(t+1)*64 + lane];
            float4 wb1 = wf4[(t+1)*64 + 32 + lane];
            float v0 = s_valid[t], v1 = s_valid[t+1];
            A.x = fmaf(wa0.x, v0, fmaf(wa1.x, v1, A.x));
            A.y = fmaf(wa0.y, v0, fmaf(wa1.y, v1, A.y));
            A.z = fmaf(wa0.z, v0, fmaf(wa1.z, v1, A.z));
            A.w = fmaf(wa0.w, v0, fmaf(wa1.w, v1, A.w));
            B.x = fmaf(wb0.x, v0, fmaf(wb1.x, v1, B.x));
            B.y = fmaf(wb0.y, v0, fmaf(wb1.y, v1, B.y));
            B.z = fmaf(wb0.z, v0, fmaf(wb1.z, v1, B.z));
            B.w = fmaf(wb0.w, v0, fmaf(wb1.w, v1, B.w));
        }
        float4* sa4 = (float4*)s_acc;
        sa4[warp*64 + lane]      = A;
        sa4[warp*64 + 32 + lane] = B;
    }
    __syncthreads();

    int bc = b*NC + c;
    {
        float q = 0.f;
        #pragma unroll
        for (int w = 0; w < 8; w++) q += s_acc[w*Dsz + tid];
        g_qpart[(size_t)bc*Dsz + tid] = q;
    }
    if (tid == 0) { g_max4[bc] = s_rm[0]; g_cnt4[bc] = s_rc[0]; }
}

// ---- K2: reduce q/tmax; u = q@G (thread-per-col, 16-deep load batching; BB=4, grid 128) ----
__global__ void __launch_bounds__(256)
k_qu() {
    int b0 = blockIdx.x * BB, tid = threadIdx.x;
    __shared__ __align__(16) float s_q[BB][Dsz];

    #pragma unroll
    for (int g = 0; g < BB; g++) {
        int b = b0 + g;
        float q = 0.f, cnt = 0.f, mx = -3.0e38f;
        #pragma unroll
        for (int cc = 0; cc < NC; cc++) {
            q   += g_qpart[(size_t)(b*NC + cc)*Dsz + tid];
            cnt += g_cnt4[b*NC + cc];
            mx   = fmaxf(mx, g_max4[b*NC + cc]);
        }
        s_q[g][tid] = q / fmaxf(cnt, 1.f);
        if (tid == 0) g_tmax[b] = mx;
    }
    __syncthreads();

    // u[g][d2=tid] = sum_i q[g][i] * G[i][d2] — 16 LDG in flight per group
    {
        float a[BB] = {0.f, 0.f, 0.f, 0.f};
        const float* Gp = g_G + tid;
        for (int i = 0; i < Dsz; i += 16) {
            float w[16];
            #pragma unroll
            for (int k = 0; k < 16; k++) w[k] = Gp[(size_t)(i+k)*Dsz];
            #pragma unroll
            for (int k = 0; k < 16; k++) {
                float q0 = s_q[0][i+k], q1 = s_q[1][i+k];
                float q2 = s_q[2][i+k], q3 = s_q[3][i+k];
                a[0] = fmaf(q0, w[k], a[0]);
                a[1] = fmaf(q1, w[k], a[1]);
                a[2] = fmaf(q2, w[k], a[2]);
                a[3] = fmaf(q3, w[k], a[3]);
            }
        }
        #pragma unroll
        for (int g = 0; g < BB; g++) g_u[(size_t)(b0+g)*Dsz + tid] = a[g];
    }
}

// ---------------- K3: pass B partials (grid: NC x Bsz) — joint two-row rescale (champion) ----------------
__global__ void __launch_bounds__(256)
k3a(const float* __restrict__ wf, const float* __restrict__ ts,
    const unsigned char* __restrict__ pad) {
    int c = blockIdx.x, b = blockIdx.y;
    int tid = threadIdx.x;
    int warp = tid >> 5, lane = tid & 31;
    int t0 = c * CROWS;

    __shared__ float s_lam[CROWS];
    __shared__ float s_valid[CROWS];
    __shared__ float s_m[8], s_Z[8], s_S[8];
    __shared__ __align__(16) float s_yp[8*Dsz];

    float tmaxv = g_tmax[b];
    if (tid < CROWS) {
        float v = pad[b*Tsz + t0 + tid] ? 0.f : 1.f;
        float dt = fmaxf(tmaxv - ts[b*Tsz + t0 + tid], 0.f) * (1.f/86400.f);
        s_lam[tid] = __expf(-0.5f*dt) * v;
        s_valid[tid] = v;
    }
    __syncthreads();

    const float4* u4 = (const float4*)(g_u + (size_t)b*Dsz);
    float4 ua = u4[lane], ub = u4[lane + 32];
    const float4* wf4 = (const float4*)(wf + (size_t)b*Tsz*Dsz + (size_t)t0*Dsz);

    float m = -3.0e38f, Z = 0.f, S = 0.f;
    float4 ya = make_float4(0.f,0.f,0.f,0.f);
    float4 yb = make_float4(0.f,0.f,0.f,0.f);

    #pragma unroll 2
    for (int t = warp*2; t < CROWS; t += 16) {
        float4 wa0 = wf4[t*64 + lane];
        float4 wb0 = wf4[t*64 + 32 + lane];
        float4 wa1 = wf4[(t+1)*64 + lane];
        float4 wb1 = wf4[(t+1)*64 + 32 + lane];
        float d0 = wa0.x*ua.x + wa0.y*ua.y + wa0.z*ua.z + wa0.w*ua.w
                 + wb0.x*ub.x + wb0.y*ub.y + wb0.z*ub.z + wb0.w*ub.w;
        float d1 = wa1.x*ua.x + wa1.y*ua.y + wa1.z*ua.z + wa1.w*ua.w
                 + wb1.x*ub.x + wb1.y*ub.y + wb1.z*ub.z + wb1.w*ub.w;
        #pragma unroll
        for (int o = 16; o > 0; o >>= 1) {
            d0 += __shfl_xor_sync(0xffffffffu, d0, o);
            d1 += __shfl_xor_sync(0xffffffffu, d1, o);
        }
        float s0 = d0 * 0.0625f;
        float s1 = d1 * 0.0625f;
        float nm = fmaxf(m, fmaxf(s0, s1));
        float sc = __expf(m - nm);
        float e0 = __expf(s0 - nm);
        float e1 = __expf(s1 - nm);
        float v0 = s_valid[t], v1 = s_valid[t+1];
        float g0 = s_lam[t]   * e0;
        float g1 = s_lam[t+1] * e1;
        Z = fmaf(Z, sc, fmaf(v0, e0, v1*e1));
        S = fmaf(S, sc, g0 + g1);
        ya.x = fmaf(ya.x, sc, fmaf(g0, wa0.x, g1*wa1.x));
        ya.y = fmaf(ya.y, sc, fmaf(g0, wa0.y, g1*wa1.y));
        ya.z = fmaf(ya.z, sc, fmaf(g0, wa0.z, g1*wa1.z));
        ya.w = fmaf(ya.w, sc, fmaf(g0, wa0.w, g1*wa1.w));
        yb.x = fmaf(yb.x, sc, fmaf(g0, wb0.x, g1*wb1.x));
        yb.y = fmaf(yb.y, sc, fmaf(g0, wb0.y, g1*wb1.y));
        yb.z = fmaf(yb.z, sc, fmaf(g0, wb0.z, g1*wb1.z));
        yb.w = fmaf(yb.w, sc, fmaf(g0, wb0.w, g1*wb1.w));
        m = nm;
    }

    if (lane == 0) s_m[warp] = m;
    __syncthreads();
    float M = s_m[0];
    #pragma unroll
    for (int w = 1; w < 8; w++) M = fmaxf(M, s_m[w]);
    float scw = __expf(m - M);
    if (lane == 0) { s_Z[warp] = Z*scw; s_S[warp] = S*scw; }
    {
        float4* syp4 = (float4*)s_yp;
        syp4[warp*64 + lane]      = make_float4(ya.x*scw, ya.y*scw, ya.z*scw, ya.w*scw);
        syp4[warp*64 + 32 + lane] = make_float4(yb.x*scw, yb.y*scw, yb.z*scw, yb.w*scw);
    }
    __syncthreads();

    int bc = b*NC + c;
    {
        float yv = 0.f;
        #pragma unroll
        for (int w = 0; w < 8; w++) yv += s_yp[w*Dsz + tid];
        g_ypart[(size_t)bc*Dsz + tid] = yv;
    }
    if (tid == 0) {
        float Zt = 0.f, St = 0.f;
        #pragma unroll
        for (int w = 0; w < 8; w++) { Zt += s_Z[w]; St += s_S[w]; }
        g_m4[bc] = M; g_Z4[bc] = Zt; g_S4[bc] = St;
    }
}

// ---- K4: combine + L = y@WVt (thread-per-e, 16-deep load batching) + register-local epilogue ----
__global__ void __launch_bounds__(256)
k4(const float* __restrict__ prevL, const float* __restrict__ prevM,
   const float* __restrict__ clsw, const float* __restrict__ clsb,
   float* __restrict__ out) {
    int b0 = blockIdx.x * BB, tid = threadIdx.x;
    int warp = tid >> 5, lane = tid & 31;
    __shared__ __align__(16) float s_y[BB][Dsz];
    __shared__ float s_w1[BB][8], s_w2[BB][8];

    #pragma unroll
    for (int g = 0; g < BB; g++) {
        int b = b0 + g;
        float m0 = g_m4[b*NC+0], m1 = g_m4[b*NC+1], m2 = g_m4[b*NC+2], m3 = g_m4[b*NC+3];
        float M = fmaxf(fmaxf(m0, m1), fmaxf(m2, m3));
        float c0 = __expf(m0 - M), c1 = __expf(m1 - M), c2 = __expf(m2 - M), c3 = __expf(m3 - M);
        float Zt = g_Z4[b*NC+0]*c0 + g_Z4[b*NC+1]*c1 + g_Z4[b*NC+2]*c2 + g_Z4[b*NC+3]*c3;
        float St = g_S4[b*NC+0]*c0 + g_S4[b*NC+1]*c1 + g_S4[b*NC+2]*c2 + g_S4[b*NC+3]*c3;
        float yv = g_ypart[(size_t)(b*NC+0)*Dsz+tid]*c0 + g_ypart[(size_t)(b*NC+1)*Dsz+tid]*c1
                 + g_ypart[(size_t)(b*NC+2)*Dsz+tid]*c2 + g_ypart[(size_t)(b*NC+3)*Dsz+tid]*c3;
        float denom = St + 1e-8f*Zt;
        float inv = denom > 0.f ? 1.f/denom : 0.f;
        s_y[g][tid] = yv * inv;
    }
    __syncthreads();

    // L[g][e=tid] = sum_d y[g][d] * WVt[d][e] — 16 LDG in flight per group
    float a[BB] = {0.f, 0.f, 0.f, 0.f};
    {
        const float* Wp = g_WVt + tid;
        for (int i = 0; i < Dsz; i += 16) {
            float w[16];
            #pragma unroll
            for (int k = 0; k < 16; k++) w[k] = Wp[(size_t)(i+k)*Dsz];
            #pragma unroll
            for (int k = 0; k < 16; k++) {
                float y0 = s_y[0][i+k], y1 = s_y[1][i+k];
                float y2 = s_y[2][i+k], y3 = s_y[3][i+k];
                a[0] = fmaf(y0, w[k], a[0]);
                a[1] = fmaf(y1, w[k], a[1]);
                a[2] = fmaf(y2, w[k], a[2]);
                a[3] = fmaf(y3, w[k], a[3]);
            }
        }
    }

    // epilogue (L value lives in a[g] at e=tid — no smem roundtrip)
    float cw1 = clsw[tid], cw2 = clsw[Dsz + tid];
    float dlg[BB];
    #pragma unroll
    for (int g = 0; g < BB; g++) {
        int b = b0 + g;
        float dl = a[g] - prevL[(size_t)b*Dsz + tid];
        dlg[g] = dl;
        float r1 = dl*dl;
        float r2 = fmaf(a[g], cw1, dl*cw2);
        #pragma unroll
        for (int o = 16; o > 0; o >>= 1) {
            r1 += __shfl_xor_sync(0xffffffffu, r1, o);
            r2 += __shfl_xor_sync(0xffffffffu, r2, o);
        }
        if (lane == 0) { s_w1[g][warp] = r1; s_w2[g][warp] = r2; }
    }
    __syncthreads();
    #pragma unroll
    for (int g = 0; g < BB; g++) {
        int b = b0 + g;
        size_t te = (size_t)OFF_TE + (size_t)b*513;
        out[te + tid]       = a[g];
        out[te + 256 + tid] = dlg[g];
        out[OFF_L + (size_t)b*Dsz + tid] = a[g];
        if (tid == 0) {
            float R1 = 0.f, R2 = 0.f;
            #pragma unroll
            for (int w = 0; w < 8; w++) { R1 += s_w1[g][w]; R2 += s_w2[g][w]; }
            float Mt = 0.9f*prevM[b] + 0.1f*sqrtf(R1);
            out[OFF_M + b] = Mt;
            out[te + 512]  = Mt;
            out[b] = R2 + Mt*clsw[2*Dsz] + clsb[0];
        }
    }
}

extern "C" void kernel_launch(void* const* d_in, const int* in_sizes, int n_in,
                              void* d_out, int out_size) {
    const float*         wf    = (const float*)d_in[0];
    const float*         ts    = (const float*)d_in[1];
    const float*         prevL = (const float*)d_in[2];
    const float*         prevM = (const float*)d_in[3];
    const unsigned char* pad   = (const unsigned char*)d_in[4];
    const float*         WQ    = (const float*)d_in[5];
    const float*         WK    = (const float*)d_in[6];
    const float*         WV    = (const float*)d_in[7];
    const float*         clsw  = (const float*)d_in[8];
    const float*         clsb  = (const float*)d_in[9];
    float* out = (float*)d_out;

    k1a <<<dim3(NC+1, Bsz), 256>>>(wf, ts, pad, WQ, WK, WV);
    k_qu<<<Bsz/BB, 256>>>();
    k3a <<<dim3(NC, Bsz), 256>>>(wf, ts, pad);
    k4  <<<Bsz/BB, 256>>>(prevL, prevM, clsw, clsb, out);
}

// round 16
// speedup vs baseline: 1.1579x; 1.0643x over previous
#include <cuda_runtime.h>
#include <math.h>

#define Bsz 512
#define Tsz 512
#define Dsz 256
#define NC  4           // T-chunks per batch row
#define CROWS (Tsz/NC)  // 128 rows per chunk

// out = [p (512) | T_event (512x513) | L_t (512x256) | M_t (512)]
#define OFF_TE 512
#define OFF_L  (512 + 512*513)
#define OFF_M  (OFF_L + 512*256)

__device__ __align__(16) float g_qpart[Bsz*NC*Dsz];
__device__ float g_cnt4[Bsz*NC];
__device__ float g_max4[Bsz*NC];
__device__ float g_tmax[Bsz];
__device__ __align__(16) float g_u[Bsz*Dsz];
__device__ __align__(16) float g_ypart[Bsz*NC*Dsz];
__device__ float g_m4[Bsz*NC], g_Z4[Bsz*NC], g_S4[Bsz*NC];
__device__ int g_sem1[Bsz];   // zero-init; reset by trailing CTA each run

// ======= K1: pass-A stream (champion loop) + trailing (q, tmax, Q=q@WQ^T, u=Q@WK) =======
__global__ void __launch_bounds__(256)
k1(const float* __restrict__ wf, const float* __restrict__ ts,
   const unsigned char* __restrict__ pad,
   const float* __restrict__ WQ, const float* __restrict__ WK) {
    int c = blockIdx.x, b = blockIdx.y;
    int tid = threadIdx.x;
    int warp = tid >> 5, lane = tid & 31;
    int t0 = c * CROWS;

    __shared__ float s_valid[CROWS];
    __shared__ float s_rm[CROWS], s_rc[CROWS];
    __shared__ __align__(16) float s_acc[8*Dsz];
    __shared__ __align__(16) float s_q[Dsz];
    __shared__ __align__(16) float s_Q[Dsz];
    __shared__ int s_last;

    if (tid < CROWS) {
        float v = pad[b*Tsz + t0 + tid] ? 0.f : 1.f;
        s_valid[tid] = v;
        float tv = ts[b*Tsz + t0 + tid];
        s_rm[tid] = (v > 0.f) ? tv : -3.0e38f;
        s_rc[tid] = v;
    }
    __syncthreads();
    for (int s = CROWS/2; s > 0; s >>= 1) {
        if (tid < s) {
            s_rm[tid] = fmaxf(s_rm[tid], s_rm[tid+s]);
            s_rc[tid] += s_rc[tid+s];
        }
        __syncthreads();
    }

    // ---- stream chunk: warp-per-row, 2 rows in flight (champion loop) ----
    const float4* wf4 = (const float4*)(wf + (size_t)b*Tsz*Dsz + (size_t)t0*Dsz);
    {
        float4 A = make_float4(0.f,0.f,0.f,0.f);
        float4 B = make_float4(0.f,0.f,0.f,0.f);
        #pragma unroll 4
        for (int t = warp*2; t < CROWS; t += 16) {
            float4 wa0 = wf4[t*64 + lane];
            float4 wb0 = wf4[t*64 + 32 + lane];
            float4 wa1 = wf4[(t+1)*64 + lane];
            float4 wb1 = wf4[(t+1)*64 + 32 + lane];
            float v0 = s_valid[t], v1 = s_valid[t+1];
            A.x = fmaf(wa0.x, v0, fmaf(wa1.x, v1, A.x));
            A.y = fmaf(wa0.y, v0, fmaf(wa1.y, v1, A.y));
            A.z = fmaf(wa0.z, v0, fmaf(wa1.z, v1, A.z));
            A.w = fmaf(wa0.w, v0, fmaf(wa1.w, v1, A.w));
            B.x = fmaf(wb0.x, v0, fmaf(wb1.x, v1, B.x));
            B.y = fmaf(wb0.y, v0, fmaf(wb1.y, v1, B.y));
            B.z = fmaf(wb0.z, v0, fmaf(wb1.z, v1, B.z));
            B.w = fmaf(wb0.w, v0, fmaf(wb1.w, v1, B.w));
        }
        float4* sa4 = (float4*)s_acc;
        sa4[warp*64 + lane]      = A;
        sa4[warp*64 + 32 + lane] = B;
    }
    __syncthreads();

    int bc = b*NC + c;
    {
        float q = 0.f;
        #pragma unroll
        for (int w = 0; w < 8; w++) q += s_acc[w*Dsz + tid];
        g_qpart[(size_t)bc*Dsz + tid] = q;
    }
    if (tid == 0) { g_max4[bc] = s_rm[0]; g_cnt4[bc] = s_rc[0]; }

    // ---- trailing-CTA election (R8-proven pattern) ----
    __threadfence();
    if (tid == 0) s_last = (atomicAdd(&g_sem1[b], 1) == NC - 1) ? 1 : 0;
    __syncthreads();
    if (!s_last) return;

    {
        float q = 0.f, cnt = 0.f, mx = -3.0e38f;
        #pragma unroll
        for (int cc = 0; cc < NC; cc++) {
            q   += g_qpart[(size_t)(b*NC + cc)*Dsz + tid];
            cnt += g_cnt4[b*NC + cc];
            mx   = fmaxf(mx, g_max4[b*NC + cc]);
        }
        s_q[tid] = q / fmaxf(cnt, 1.f);
        if (tid == 0) g_tmax[b] = mx;
    }
    __syncthreads();

    // Q[e] = sum_d q[d]*WQ[e,d] — warp per row, 2 rows in flight (low reg peak)
    {
        const float4* q4 = (const float4*)s_q;
        float4 qA = q4[lane*2], qB = q4[lane*2 + 1];
        #pragma unroll 2
        for (int i = 0; i < 32; i += 2) {
            int e0 = warp*32 + i, e1 = e0 + 1;
            const float4* wr0 = (const float4*)(WQ + (size_t)e0*Dsz);
            const float4* wr1 = (const float4*)(WQ + (size_t)e1*Dsz);
            float4 w0A = wr0[lane*2], w0B = wr0[lane*2+1];
            float4 w1A = wr1[lane*2], w1B = wr1[lane*2+1];
            float d0 = w0A.x*qA.x + w0A.y*qA.y + w0A.z*qA.z + w0A.w*qA.w
                     + w0B.x*qB.x + w0B.y*qB.y + w0B.z*qB.z + w0B.w*qB.w;
            float d1 = w1A.x*qA.x + w1A.y*qA.y + w1A.z*qA.z + w1A.w*qA.w
                     + w1B.x*qB.x + w1B.y*qB.y + w1B.z*qB.z + w1B.w*qB.w;
            #pragma unroll
            for (int o = 16; o > 0; o >>= 1) {
                d0 += __shfl_xor_sync(0xffffffffu, d0, o);
                d1 += __shfl_xor_sync(0xffffffffu, d1, o);
            }
            if (lane == 0) { s_Q[e0] = d0; s_Q[e1] = d1; }
        }
    }
    __syncthreads();

    // u[d2] = sum_e Q[e]*WK[e,d2] — threads over d2 (coalesced)
    {
        float a = 0.f;
        const float* Wp = WK + tid;
        #pragma unroll 8
        for (int e = 0; e < Dsz; e++)
            a = fmaf(s_Q[e], __ldg(Wp + (size_t)e*Dsz), a);
        g_u[(size_t)b*Dsz + tid] = a;
    }
    if (tid == 0) g_sem1[b] = 0;   // reset for next graph replay
}

// ---------------- K3: pass B partials (grid: NC x Bsz) — joint two-row rescale (champion) ----------------
__global__ void __launch_bounds__(256)
k3a(const float* __restrict__ wf, const float* __restrict__ ts,
    const unsigned char* __restrict__ pad) {
    int c = blockIdx.x, b = blockIdx.y;
    int tid = threadIdx.x;
    int warp = tid >> 5, lane = tid & 31;
    int t0 = c * CROWS;

    __shared__ float s_lam[CROWS];
    __shared__ float s_valid[CROWS];
    __shared__ float s_m[8], s_Z[8], s_S[8];
    __shared__ __align__(16) float s_yp[8*Dsz];

    float tmaxv = g_tmax[b];
    if (tid < CROWS) {
        float v = pad[b*Tsz + t0 + tid] ? 0.f : 1.f;
        float dt = fmaxf(tmaxv - ts[b*Tsz + t0 + tid], 0.f) * (1.f/86400.f);
        s_lam[tid] = __expf(-0.5f*dt) * v;
        s_valid[tid] = v;
    }
    __syncthreads();

    const float4* u4 = (const float4*)(g_u + (size_t)b*Dsz);
    float4 ua = u4[lane], ub = u4[lane + 32];
    const float4* wf4 = (const float4*)(wf + (size_t)b*Tsz*Dsz + (size_t)t0*Dsz);

    float m = -3.0e38f, Z = 0.f, S = 0.f;
    float4 ya = make_float4(0.f,0.f,0.f,0.f);
    float4 yb = make_float4(0.f,0.f,0.f,0.f);

    #pragma unroll 2
    for (int t = warp*2; t < CROWS; t += 16) {
        float4 wa0 = wf4[t*64 + lane];
        float4 wb0 = wf4[t*64 + 32 + lane];
        float4 wa1 = wf4[(t+1)*64 + lane];
        float4 wb1 = wf4[(t+1)*64 + 32 + lane];
        float d0 = wa0.x*ua.x + wa0.y*ua.y + wa0.z*ua.z + wa0.w*ua.w
                 + wb0.x*ub.x + wb0.y*ub.y + wb0.z*ub.z + wb0.w*ub.w;
        float d1 = wa1.x*ua.x + wa1.y*ua.y + wa1.z*ua.z + wa1.w*ua.w
                 + wb1.x*ub.x + wb1.y*ub.y + wb1.z*ub.z + wb1.w*ub.w;
        #pragma unroll
        for (int o = 16; o > 0; o >>= 1) {
            d0 += __shfl_xor_sync(0xffffffffu, d0, o);
            d1 += __shfl_xor_sync(0xffffffffu, d1, o);
        }
        float s0 = d0 * 0.0625f;
        float s1 = d1 * 0.0625f;
        float nm = fmaxf(m, fmaxf(s0, s1));
        float sc = __expf(m - nm);
        float e0 = __expf(s0 - nm);
        float e1 = __expf(s1 - nm);
        float v0 = s_valid[t], v1 = s_valid[t+1];
        float g0 = s_lam[t]   * e0;
        float g1 = s_lam[t+1] * e1;
        Z = fmaf(Z, sc, fmaf(v0, e0, v1*e1));
        S = fmaf(S, sc, g0 + g1);
        ya.x = fmaf(ya.x, sc, fmaf(g0, wa0.x, g1*wa1.x));
        ya.y = fmaf(ya.y, sc, fmaf(g0, wa0.y, g1*wa1.y));
        ya.z = fmaf(ya.z, sc, fmaf(g0, wa0.z, g1*wa1.z));
        ya.w = fmaf(ya.w, sc, fmaf(g0, wa0.w, g1*wa1.w));
        yb.x = fmaf(yb.x, sc, fmaf(g0, wb0.x, g1*wb1.x));
        yb.y = fmaf(yb.y, sc, fmaf(g0, wb0.y, g1*wb1.y));
        yb.z = fmaf(yb.z, sc, fmaf(g0, wb0.z, g1*wb1.z));
        yb.w = fmaf(yb.w, sc, fmaf(g0, wb0.w, g1*wb1.w));
        m = nm;
    }

    if (lane == 0) s_m[warp] = m;
    __syncthreads();
    float M = s_m[0];
    #pragma unroll
    for (int w = 1; w < 8; w++) M = fmaxf(M, s_m[w]);
    float scw = __expf(m - M);
    if (lane == 0) { s_Z[warp] = Z*scw; s_S[warp] = S*scw; }
    {
        float4* syp4 = (float4*)s_yp;
        syp4[warp*64 + lane]      = make_float4(ya.x*scw, ya.y*scw, ya.z*scw, ya.w*scw);
        syp4[warp*64 + 32 + lane] = make_float4(yb.x*scw, yb.y*scw, yb.z*scw, yb.w*scw);
    }
    __syncthreads();

    int bc = b*NC + c;
    {
        float yv = 0.f;
        #pragma unroll
        for (int w = 0; w < 8; w++) yv += s_yp[w*Dsz + tid];
        g_ypart[(size_t)bc*Dsz + tid] = yv;
    }
    if (tid == 0) {
        float Zt = 0.f, St = 0.f;
        #pragma unroll
        for (int w = 0; w < 8; w++) { Zt += s_Z[w]; St += s_S[w]; }
        g_m4[bc] = M; g_Z4[bc] = Zt; g_S4[bc] = St;
    }
}

// ---------------- K4: combine y + L = y@WV^T + epilogue (2 b per block, grid 256) — champion ----------------
__global__ void __launch_bounds__(256)
k4(const float* __restrict__ WV, const float* __restrict__ prevL,
   const float* __restrict__ prevM, const float* __restrict__ clsw,
   const float* __restrict__ clsb, float* __restrict__ out) {
    int b0 = blockIdx.x * 2, tid = threadIdx.x;
    int warp = tid >> 5, lane = tid & 31;
    __shared__ __align__(16) float s_yf[2][Dsz];
    __shared__ __align__(16) float s_L[2][Dsz];
    __shared__ float s_w1[2][8], s_w2[2][8];

    #pragma unroll
    for (int g = 0; g < 2; g++) {
        int b = b0 + g;
        float m0 = g_m4[b*NC+0], m1 = g_m4[b*NC+1], m2 = g_m4[b*NC+2], m3 = g_m4[b*NC+3];
        float M = fmaxf(fmaxf(m0, m1), fmaxf(m2, m3));
        float c0 = __expf(m0 - M), c1 = __expf(m1 - M), c2 = __expf(m2 - M), c3 = __expf(m3 - M);
        float Zt = g_Z4[b*NC+0]*c0 + g_Z4[b*NC+1]*c1 + g_Z4[b*NC+2]*c2 + g_Z4[b*NC+3]*c3;
        float St = g_S4[b*NC+0]*c0 + g_S4[b*NC+1]*c1 + g_S4[b*NC+2]*c2 + g_S4[b*NC+3]*c3;
        float yv = g_ypart[(size_t)(b*NC+0)*Dsz+tid]*c0 + g_ypart[(size_t)(b*NC+1)*Dsz+tid]*c1
                 + g_ypart[(size_t)(b*NC+2)*Dsz+tid]*c2 + g_ypart[(size_t)(b*NC+3)*Dsz+tid]*c3;
        float denom = St + 1e-8f*Zt;
        float inv = denom > 0.f ? 1.f/denom : 0.f;
        s_yf[g][tid] = yv * inv;
    }
    __syncthreads();

    // GEMM: warp-per-row, 4 rows in flight (8 LDG.128 outstanding), 2 b reuse
    {
        const float4* y0 = (const float4*)s_yf[0];
        const float4* y1 = (const float4*)s_yf[1];
        float4 y0A = y0[lane*2], y0B = y0[lane*2+1];
        float4 y1A = y1[lane*2], y1B = y1[lane*2+1];
        #pragma unroll 2
        for (int i = 0; i < 32; i += 4) {
            float4 wA[4], wB[4];
            #pragma unroll
            for (int j = 0; j < 4; j++) {
                const float4* wr = (const float4*)(WV + (size_t)(warp*32 + i + j)*Dsz);
                wA[j] = wr[lane*2]; wB[j] = wr[lane*2+1];
            }
            float d[8];
            #pragma unroll
            for (int j = 0; j < 4; j++) {
                d[j]   = wA[j].x*y0A.x + wA[j].y*y0A.y + wA[j].z*y0A.z + wA[j].w*y0A.w
                       + wB[j].x*y0B.x + wB[j].y*y0B.y + wB[j].z*y0B.z + wB[j].w*y0B.w;
                d[4+j] = wA[j].x*y1A.x + wA[j].y*y1A.y + wA[j].z*y1A.z + wA[j].w*y1A.w
                       + wB[j].x*y1B.x + wB[j].y*y1B.y + wB[j].z*y1B.z + wB[j].w*y1B.w;
            }
            #pragma unroll
            for (int o = 16; o > 0; o >>= 1) {
                #pragma unroll
                for (int k = 0; k < 8; k++) d[k] += __shfl_xor_sync(0xffffffffu, d[k], o);
            }
            if (lane == 0) {
                #pragma unroll
                for (int j = 0; j < 4; j++) {
                    s_L[0][warp*32 + i + j] = d[j];
                    s_L[1][warp*32 + i + j] = d[4+j];
                }
            }
        }
    }
    __syncthreads();

    float cw1 = clsw[tid], cw2 = clsw[Dsz + tid];
    float Lg[2], dlg[2];
    #pragma unroll
    for (int g = 0; g < 2; g++) {
        int b = b0 + g;
        float L  = s_L[g][tid];
        float dl = L - prevL[(size_t)b*Dsz + tid];
        Lg[g] = L; dlg[g] = dl;
        float r1 = dl*dl;
        float r2 = fmaf(L, cw1, dl*cw2);
        #pragma unroll
        for (int o = 16; o > 0; o >>= 1) {
            r1 += __shfl_xor_sync(0xffffffffu, r1, o);
            r2 += __shfl_xor_sync(0xffffffffu, r2, o);
        }
        if (lane == 0) { s_w1[g][warp] = r1; s_w2[g][warp] = r2; }
    }
    __syncthreads();
    #pragma unroll
    for (int g = 0; g < 2; g++) {
        int b = b0 + g;
        size_t te = (size_t)OFF_TE + (size_t)b*513;
        out[te + tid]       = Lg[g];
        out[te + 256 + tid] = dlg[g];
        out[OFF_L + (size_t)b*Dsz + tid] = Lg[g];
        if (tid == 0) {
            float R1 = 0.f, R2 = 0.f;
            #pragma unroll
            for (int w = 0; w < 8; w++) { R1 += s_w1[g][w]; R2 += s_w2[g][w]; }
            float Mt = 0.9f*prevM[b] + 0.1f*sqrtf(R1);
            out[OFF_M + b] = Mt;
            out[te + 512]  = Mt;
            out[b] = R2 + Mt*clsw[2*Dsz] + clsb[0];
        }
    }
}

extern "C" void kernel_launch(void* const* d_in, const int* in_sizes, int n_in,
                              void* d_out, int out_size) {
    const float*         wf    = (const float*)d_in[0];
    const float*         ts    = (const float*)d_in[1];
    const float*         prevL = (const float*)d_in[2];
    const float*         prevM = (const float*)d_in[3];
    const unsigned char* pad   = (const unsigned char*)d_in[4];
    const float*         WQ    = (const float*)d_in[5];
    const float*         WK    = (const float*)d_in[6];
    const float*         WV    = (const float*)d_in[7];
    const float*         clsw  = (const float*)d_in[8];
    const float*         clsb  = (const float*)d_in[9];
    float* out = (float*)d_out;

    k1 <<<dim3(NC, Bsz), 256>>>(wf, ts, pad, WQ, WK);
    k3a<<<dim3(NC, Bsz), 256>>>(wf, ts, pad);
    k4 <<<Bsz/2, 256>>>(WV, prevL, prevM, clsw, clsb, out);
}

// round 17
// speedup vs baseline: 1.3017x; 1.1242x over previous
#include <cuda_runtime.h>
#include <math.h>

#define Bsz 512
#define Tsz 512
#define Dsz 256
#define NC  4           // T-chunks per batch row
#define CROWS (Tsz/NC)  // 128 rows per chunk

// out = [p (512) | T_event (512x513) | L_t (512x256) | M_t (512)]
#define OFF_TE 512
#define OFF_L  (512 + 512*513)
#define OFF_M  (OFF_L + 512*256)

__device__ __align__(16) float g_qpart[Bsz*NC*Dsz];
__device__ float g_cnt4[Bsz*NC];
__device__ float g_max4[Bsz*NC];
__device__ float g_tmax[Bsz];
__device__ __align__(16) float g_u[Bsz*Dsz];
__device__ __align__(16) float g_ypart[Bsz*NC*Dsz];
__device__ float g_m4[Bsz*NC], g_Z4[Bsz*NC], g_S4[Bsz*NC];
__device__ int g_sem1[Bsz];   // zero-init; reset by trailing CTA each run

// ======= K1: pass-A stream (champion loop) + trailing (q, tmax, Q=q@WQ^T, u=Q@WK) =======
__global__ void __launch_bounds__(256)
k1(const float* __restrict__ wf, const float* __restrict__ ts,
   const unsigned char* __restrict__ pad,
   const float* __restrict__ WQ, const float* __restrict__ WK) {
    int c = blockIdx.x, b = blockIdx.y;
    int tid = threadIdx.x;
    int warp = tid >> 5, lane = tid & 31;
    int t0 = c * CROWS;

    __shared__ float s_valid[CROWS];
    __shared__ float s_rm[CROWS], s_rc[CROWS];
    __shared__ __align__(16) float s_acc[8*Dsz];
    __shared__ __align__(16) float s_q[Dsz];
    __shared__ __align__(16) float s_Q[Dsz];
    __shared__ int s_last;

    if (tid < CROWS) {
        float v = pad[b*Tsz + t0 + tid] ? 0.f : 1.f;
        s_valid[tid] = v;
        float tv = ts[b*Tsz + t0 + tid];
        s_rm[tid] = (v > 0.f) ? tv : -3.0e38f;
        s_rc[tid] = v;
    }
    __syncthreads();
    for (int s = CROWS/2; s > 0; s >>= 1) {
        if (tid < s) {
            s_rm[tid] = fmaxf(s_rm[tid], s_rm[tid+s]);
            s_rc[tid] += s_rc[tid+s];
        }
        __syncthreads();
    }

    // ---- stream chunk: warp-per-row, 2 rows in flight (champion loop) ----
    const float4* wf4 = (const float4*)(wf + (size_t)b*Tsz*Dsz + (size_t)t0*Dsz);
    {
        float4 A = make_float4(0.f,0.f,0.f,0.f);
        float4 B = make_float4(0.f,0.f,0.f,0.f);
        #pragma unroll 4
        for (int t = warp*2; t < CROWS; t += 16) {
            float4 wa0 = wf4[t*64 + lane];
            float4 wb0 = wf4[t*64 + 32 + lane];
            float4 wa1 = wf4[(t+1)*64 + lane];
            float4 wb1 = wf4[(t+1)*64 + 32 + lane];
            float v0 = s_valid[t], v1 = s_valid[t+1];
            A.x = fmaf(wa0.x, v0, fmaf(wa1.x, v1, A.x));
            A.y = fmaf(wa0.y, v0, fmaf(wa1.y, v1, A.y));
            A.z = fmaf(wa0.z, v0, fmaf(wa1.z, v1, A.z));
            A.w = fmaf(wa0.w, v0, fmaf(wa1.w, v1, A.w));
            B.x = fmaf(wb0.x, v0, fmaf(wb1.x, v1, B.x));
            B.y = fmaf(wb0.y, v0, fmaf(wb1.y, v1, B.y));
            B.z = fmaf(wb0.z, v0, fmaf(wb1.z, v1, B.z));
            B.w = fmaf(wb0.w, v0, fmaf(wb1.w, v1, B.w));
        }
        float4* sa4 = (float4*)s_acc;
        sa4[warp*64 + lane]      = A;
        sa4[warp*64 + 32 + lane] = B;
    }
    __syncthreads();

    int bc = b*NC + c;
    {
        float q = 0.f;
        #pragma unroll
        for (int w = 0; w < 8; w++) q += s_acc[w*Dsz + tid];
        g_qpart[(size_t)bc*Dsz + tid] = q;
    }
    if (tid == 0) { g_max4[bc] = s_rm[0]; g_cnt4[bc] = s_rc[0]; }

    // ---- trailing-CTA election ----
    __threadfence();
    if (tid == 0) s_last = (atomicAdd(&g_sem1[b], 1) == NC - 1) ? 1 : 0;
    __syncthreads();
    if (!s_last) return;

    {
        float q = 0.f, cnt = 0.f, mx = -3.0e38f;
        #pragma unroll
        for (int cc = 0; cc < NC; cc++) {
            q   += g_qpart[(size_t)(b*NC + cc)*Dsz + tid];
            cnt += g_cnt4[b*NC + cc];
            mx   = fmaxf(mx, g_max4[b*NC + cc]);
        }
        s_q[tid] = q / fmaxf(cnt, 1.f);
        if (tid == 0) g_tmax[b] = mx;
    }
    __syncthreads();

    // Q[e] = sum_d q[d]*WQ[e,d] — warp per row, 2 rows in flight (low reg peak)
    {
        const float4* q4 = (const float4*)s_q;
        float4 qA = q4[lane*2], qB = q4[lane*2 + 1];
        #pragma unroll 2
        for (int i = 0; i < 32; i += 2) {
            int e0 = warp*32 + i, e1 = e0 + 1;
            const float4* wr0 = (const float4*)(WQ + (size_t)e0*Dsz);
            const float4* wr1 = (const float4*)(WQ + (size_t)e1*Dsz);
            float4 w0A = wr0[lane*2], w0B = wr0[lane*2+1];
            float4 w1A = wr1[lane*2], w1B = wr1[lane*2+1];
            float d0 = w0A.x*qA.x + w0A.y*qA.y + w0A.z*qA.z + w0A.w*qA.w
                     + w0B.x*qB.x + w0B.y*qB.y + w0B.z*qB.z + w0B.w*qB.w;
            float d1 = w1A.x*qA.x + w1A.y*qA.y + w1A.z*qA.z + w1A.w*qA.w
                     + w1B.x*qB.x + w1B.y*qB.y + w1B.z*qB.z + w1B.w*qB.w;
            #pragma unroll
            for (int o = 16; o > 0; o >>= 1) {
                d0 += __shfl_xor_sync(0xffffffffu, d0, o);
                d1 += __shfl_xor_sync(0xffffffffu, d1, o);
            }
            if (lane == 0) { s_Q[e0] = d0; s_Q[e1] = d1; }
        }
    }
    __syncthreads();

    // u[d2] = sum_e Q[e]*WK[e,d2] — threads over d2 (coalesced)
    {
        float a = 0.f;
        const float* Wp = WK + tid;
        #pragma unroll 8
        for (int e = 0; e < Dsz; e++)
            a = fmaf(s_Q[e], __ldg(Wp + (size_t)e*Dsz), a);
        g_u[(size_t)b*Dsz + tid] = a;
    }
    if (tid == 0) g_sem1[b] = 0;   // reset for next graph replay
}

// ---- K3: pass B partials (grid: NC x Bsz) — joint two-row rescale, REVERSE b order ----
// k1 streamed b ascending, so L2 retains the highest-b ~126MB of WF at k1's end.
// Reading b descending makes k3's first waves hit L2 instead of DRAM.
__global__ void __launch_bounds__(256)
k3a(const float* __restrict__ wf, const float* __restrict__ ts,
    const unsigned char* __restrict__ pad) {
    int c = blockIdx.x;
    int b = (Bsz - 1) - blockIdx.y;      // reverse-b mapping
    int tid = threadIdx.x;
    int warp = tid >> 5, lane = tid & 31;
    int t0 = c * CROWS;

    __shared__ float s_lam[CROWS];
    __shared__ float s_valid[CROWS];
    __shared__ float s_m[8], s_Z[8], s_S[8];
    __shared__ __align__(16) float s_yp[8*Dsz];

    float tmaxv = g_tmax[b];
    if (tid < CROWS) {
        float v = pad[b*Tsz + t0 + tid] ? 0.f : 1.f;
        float dt = fmaxf(tmaxv - ts[b*Tsz + t0 + tid], 0.f) * (1.f/86400.f);
        s_lam[tid] = __expf(-0.5f*dt) * v;
        s_valid[tid] = v;
    }
    __syncthreads();

    const float4* u4 = (const float4*)(g_u + (size_t)b*Dsz);
    float4 ua = u4[lane], ub = u4[lane + 32];
    const float4* wf4 = (const float4*)(wf + (size_t)b*Tsz*Dsz + (size_t)t0*Dsz);

    float m = -3.0e38f, Z = 0.f, S = 0.f;
    float4 ya = make_float4(0.f,0.f,0.f,0.f);
    float4 yb = make_float4(0.f,0.f,0.f,0.f);

    #pragma unroll 2
    for (int t = warp*2; t < CROWS; t += 16) {
        float4 wa0 = wf4[t*64 + lane];
        float4 wb0 = wf4[t*64 + 32 + lane];
        float4 wa1 = wf4[(t+1)*64 + lane];
        float4 wb1 = wf4[(t+1)*64 + 32 + lane];
        float d0 = wa0.x*ua.x + wa0.y*ua.y + wa0.z*ua.z + wa0.w*ua.w
                 + wb0.x*ub.x + wb0.y*ub.y + wb0.z*ub.z + wb0.w*ub.w;
        float d1 = wa1.x*ua.x + wa1.y*ua.y + wa1.z*ua.z + wa1.w*ua.w
                 + wb1.x*ub.x + wb1.y*ub.y + wb1.z*ub.z + wb1.w*ub.w;
        #pragma unroll
        for (int o = 16; o > 0; o >>= 1) {
            d0 += __shfl_xor_sync(0xffffffffu, d0, o);
            d1 += __shfl_xor_sync(0xffffffffu, d1, o);
        }
        float s0 = d0 * 0.0625f;
        float s1 = d1 * 0.0625f;
        float nm = fmaxf(m, fmaxf(s0, s1));
        float sc = __expf(m - nm);
        float e0 = __expf(s0 - nm);
        float e1 = __expf(s1 - nm);
        float v0 = s_valid[t], v1 = s_valid[t+1];
        float g0 = s_lam[t]   * e0;
        float g1 = s_lam[t+1] * e1;
        Z = fmaf(Z, sc, fmaf(v0, e0, v1*e1));
        S = fmaf(S, sc, g0 + g1);
        ya.x = fmaf(ya.x, sc, fmaf(g0, wa0.x, g1*wa1.x));
        ya.y = fmaf(ya.y, sc, fmaf(g0, wa0.y, g1*wa1.y));
        ya.z = fmaf(ya.z, sc, fmaf(g0, wa0.z, g1*wa1.z));
        ya.w = fmaf(ya.w, sc, fmaf(g0, wa0.w, g1*wa1.w));
        yb.x = fmaf(yb.x, sc, fmaf(g0, wb0.x, g1*wb1.x));
        yb.y = fmaf(yb.y, sc, fmaf(g0, wb0.y, g1*wb1.y));
        yb.z = fmaf(yb.z, sc, fmaf(g0, wb0.z, g1*wb1.z));
        yb.w = fmaf(yb.w, sc, fmaf(g0, wb0.w, g1*wb1.w));
        m = nm;
    }

    if (lane == 0) s_m[warp] = m;
    __syncthreads();
    float M = s_m[0];
    #pragma unroll
    for (int w = 1; w < 8; w++) M = fmaxf(M, s_m[w]);
    float scw = __expf(m - M);
    if (lane == 0) { s_Z[warp] = Z*scw; s_S[warp] = S*scw; }
    {
        float4* syp4 = (float4*)s_yp;
        syp4[warp*64 + lane]      = make_float4(ya.x*scw, ya.y*scw, ya.z*scw, ya.w*scw);
        syp4[warp*64 + 32 + lane] = make_float4(yb.x*scw, yb.y*scw, yb.z*scw, yb.w*scw);
    }
    __syncthreads();

    int bc = b*NC + c;
    {
        float yv = 0.f;
        #pragma unroll
        for (int w = 0; w < 8; w++) yv += s_yp[w*Dsz + tid];
        g_ypart[(size_t)bc*Dsz + tid] = yv;
    }
    if (tid == 0) {
        float Zt = 0.f, St = 0.f;
        #pragma unroll
        for (int w = 0; w < 8; w++) { Zt += s_Z[w]; St += s_S[w]; }
        g_m4[bc] = M; g_Z4[bc] = Zt; g_S4[bc] = St;
    }
}

// ---------------- K4: combine y + L = y@WV^T + epilogue (2 b per block, grid 256) — champion ----------------
__global__ void __launch_bounds__(256)
k4(const float* __restrict__ WV, const float* __restrict__ prevL,
   const float* __restrict__ prevM, const float* __restrict__ clsw,
   const float* __restrict__ clsb, float* __restrict__ out) {
    int b0 = blockIdx.x * 2, tid = threadIdx.x;
    int warp = tid >> 5, lane = tid & 31;
    __shared__ __align__(16) float s_yf[2][Dsz];
    __shared__ __align__(16) float s_L[2][Dsz];
    __shared__ float s_w1[2][8], s_w2[2][8];

    #pragma unroll
    for (int g = 0; g < 2; g++) {
        int b = b0 + g;
        float m0 = g_m4[b*NC+0], m1 = g_m4[b*NC+1], m2 = g_m4[b*NC+2], m3 = g_m4[b*NC+3];
        float M = fmaxf(fmaxf(m0, m1), fmaxf(m2, m3));
        float c0 = __expf(m0 - M), c1 = __expf(m1 - M), c2 = __expf(m2 - M), c3 = __expf(m3 - M);
        float Zt = g_Z4[b*NC+0]*c0 + g_Z4[b*NC+1]*c1 + g_Z4[b*NC+2]*c2 + g_Z4[b*NC+3]*c3;
        float St = g_S4[b*NC+0]*c0 + g_S4[b*NC+1]*c1 + g_S4[b*NC+2]*c2 + g_S4[b*NC+3]*c3;
        float yv = g_ypart[(size_t)(b*NC+0)*Dsz+tid]*c0 + g_ypart[(size_t)(b*NC+1)*Dsz+tid]*c1
                 + g_ypart[(size_t)(b*NC+2)*Dsz+tid]*c2 + g_ypart[(size_t)(b*NC+3)*Dsz+tid]*c3;
        float denom = St + 1e-8f*Zt;
        float inv = denom > 0.f ? 1.f/denom : 0.f;
        s_yf[g][tid] = yv * inv;
    }
    __syncthreads();

    // GEMM: warp-per-row, 4 rows in flight (8 LDG.128 outstanding), 2 b reuse
    {
        const float4* y0 = (const float4*)s_yf[0];
        const float4* y1 = (const float4*)s_yf[1];
        float4 y0A = y0[lane*2], y0B = y0[lane*2+1];
        float4 y1A = y1[lane*2], y1B = y1[lane*2+1];
        #pragma unroll 2
        for (int i = 0; i < 32; i += 4) {
            float4 wA[4], wB[4];
            #pragma unroll
            for (int j = 0; j < 4; j++) {
                const float4* wr = (const float4*)(WV + (size_t)(warp*32 + i + j)*Dsz);
                wA[j] = wr[lane*2]; wB[j] = wr[lane*2+1];
            }
            float d[8];
            #pragma unroll
            for (int j = 0; j < 4; j++) {
                d[j]   = wA[j].x*y0A.x + wA[j].y*y0A.y + wA[j].z*y0A.z + wA[j].w*y0A.w
                       + wB[j].x*y0B.x + wB[j].y*y0B.y + wB[j].z*y0B.z + wB[j].w*y0B.w;
                d[4+j] = wA[j].x*y1A.x + wA[j].y*y1A.y + wA[j].z*y1A.z + wA[j].w*y1A.w
                       + wB[j].x*y1B.x + wB[j].y*y1B.y + wB[j].z*y1B.z + wB[j].w*y1B.w;
            }
            #pragma unroll
            for (int o = 16; o > 0; o >>= 1) {
                #pragma unroll
                for (int k = 0; k < 8; k++) d[k] += __shfl_xor_sync(0xffffffffu, d[k], o);
            }
            if (lane == 0) {
                #pragma unroll
                for (int j = 0; j < 4; j++) {
                    s_L[0][warp*32 + i + j] = d[j];
                    s_L[1][warp*32 + i + j] = d[4+j];
                }
            }
        }
    }
    __syncthreads();

    float cw1 = clsw[tid], cw2 = clsw[Dsz + tid];
    float Lg[2], dlg[2];
    #pragma unroll
    for (int g = 0; g < 2; g++) {
        int b = b0 + g;
        float L  = s_L[g][tid];
        float dl = L - prevL[(size_t)b*Dsz + tid];
        Lg[g] = L; dlg[g] = dl;
        float r1 = dl*dl;
        float r2 = fmaf(L, cw1, dl*cw2);
        #pragma unroll
        for (int o = 16; o > 0; o >>= 1) {
            r1 += __shfl_xor_sync(0xffffffffu, r1, o);
            r2 += __shfl_xor_sync(0xffffffffu, r2, o);
        }
        if (lane == 0) { s_w1[g][warp] = r1; s_w2[g][warp] = r2; }
    }
    __syncthreads();
    #pragma unroll
    for (int g = 0; g < 2; g++) {
        int b = b0 + g;
        size_t te = (size_t)OFF_TE + (size_t)b*513;
        out[te + tid]       = Lg[g];
        out[te + 256 + tid] = dlg[g];
        out[OFF_L + (size_t)b*Dsz + tid] = Lg[g];
        if (tid == 0) {
            float R1 = 0.f, R2 = 0.f;
            #pragma unroll
            for (int w = 0; w < 8; w++) { R1 += s_w1[g][w]; R2 += s_w2[g][w]; }
            float Mt = 0.9f*prevM[b] + 0.1f*sqrtf(R1);
            out[OFF_M + b] = Mt;
            out[te + 512]  = Mt;
            out[b] = R2 + Mt*clsw[2*Dsz] + clsb[0];
        }
    }
}

extern "C" void kernel_launch(void* const* d_in, const int* in_sizes, int n_in,
                              void* d_out, int out_size) {
    const float*         wf    = (const float*)d_in[0];
    const float*         ts    = (const float*)d_in[1];
    const float*         prevL = (const float*)d_in[2];
    const float*         prevM = (const float*)d_in[3];
    const unsigned char* pad   = (const unsigned char*)d_in[4];
    const float*         WQ    = (const float*)d_in[5];
    const float*         WK    = (const float*)d_in[6];
    const float*         WV    = (const float*)d_in[7];
    const float*         clsw  = (const float*)d_in[8];
    const float*         clsb  = (const float*)d_in[9];
    float* out = (float*)d_out;

    k1 <<<dim3(NC, Bsz), 256>>>(wf, ts, pad, WQ, WK);
    k3a<<<dim3(NC, Bsz), 256>>>(wf, ts, pad);
    k4 <<<Bsz/2, 256>>>(WV, prevL, prevM, clsw, clsb, out);
}